// round 8
// baseline (speedup 1.0000x reference)
#include <cuda_runtime.h>
#include <math.h>

// Problem dims (fixed by the reference)
#define NB 2048   // batch
#define NI 256    // inner / contraction dim j
#define NO 256    // output dim i

#define J_CH 64                    // j-chunk per smem stage
#define NCHUNK (NI / J_CH)         // 4
#define STR 68                     // floats per j-pair row (32*2 + 4 pad)
#define TBL ((J_CH / 2) * STR)     // 2176 floats per table

typedef unsigned long long ull;

// ---------------- packed f32x2 helpers ----------------
__device__ __forceinline__ ull ffma2(ull a, ull b, ull c) {
    ull d;
    asm("fma.rn.f32x2 %0, %1, %2, %3;" : "=l"(d) : "l"(a), "l"(b), "l"(c));
    return d;
}
__device__ __forceinline__ ull fadd2(ull a, ull b) {
    ull d;
    asm("add.rn.f32x2 %0, %1, %2;" : "=l"(d) : "l"(a), "l"(b));
    return d;
}
__device__ __forceinline__ ull fmul2(ull a, ull b) {
    ull d;
    asm("mul.rn.f32x2 %0, %1, %2;" : "=l"(d) : "l"(a), "l"(b));
    return d;
}
__device__ __forceinline__ float2 u2f(ull v) {
    float2 r;
    asm("mov.b64 {%0, %1}, %2;" : "=f"(r.x), "=f"(r.y) : "l"(v));
    return r;
}
__device__ __forceinline__ float frcp(float x) {
    float r;
    asm("rcp.approx.f32 %0, %1;" : "=f"(r) : "f"(x));
    return r;
}

// 4 j-terms fused: sum 1/d = (S.x*P.y + S.y*P.x) * rcp(P.x*P.y), S=D+E, P=D*E.
#define QCELL(acc, cA, sA, cB, sB, nA, oA, nB, oB)                     \
    do {                                                               \
        ull D_ = ffma2((cA), (nA), ffma2((sA), (oA), Q2));             \
        ull E_ = ffma2((cB), (nB), ffma2((sB), (oB), Q2));             \
        float2 S_ = u2f(fadd2(D_, E_));                                \
        float2 P_ = u2f(fmul2(D_, E_));                                \
        (acc) = fmaf(fmaf(S_.x, P_.y, S_.y * P_.x),                    \
                     frcp(P_.x * P_.y), (acc));                        \
    } while (0)

// CTA: 64 threads, tile 32(b) x 32(i), micro-tile 4b x 4i (16 accumulators).
// grid (64, 8) = 512 CTAs. ILP-driven latency hiding: 16 indep chains/thread.
__global__ __launch_bounds__(64) void photonic_fused(
        float* __restrict__ out,
        const float* __restrict__ x, const float* __restrict__ off,
        float phi0, float two_rho, ull Q2, float negK) {
    __shared__ __align__(16) float s_cx[TBL];
    __shared__ __align__(16) float s_sx[TBL];
    __shared__ __align__(16) float s_nc[TBL];
    __shared__ __align__(16) float s_so[TBL];

    const int t  = threadIdx.x;                 // 0..63
    const int tx = t & 7;                       // 8 groups along b (4 b each)
    const int ty = t >> 3;                      // 8 groups along i (4 i each)
    const int b_blk = blockIdx.x * 32;
    const int i_blk = blockIdx.y * 32;

    // fill coords: thread owns j = t within the chunk
    const int par = t & 1;
    const int jph = t >> 1;

    float acc[16];
    #pragma unroll
    for (int k = 0; k < 16; ++k) acc[k] = 0.f;

    for (int chunk = 0; chunk < NCHUNK; ++chunk) {
        const int j_base = chunk * J_CH;
        __syncthreads();                        // prior reads done

        // x-side: 32 b-rows for this thread's j (coalesced 64-float rows)
        const float* px = x + b_blk * NI + j_base + t;
        #pragma unroll 8
        for (int r = 0; r < 32; ++r) {
            float s, c;
            __sincosf(phi0 + px[r * NI], &s, &c);
            s_cx[jph * STR + r * 2 + par] = c;
            s_sx[jph * STR + r * 2 + par] = s;
        }
        // o-side: 32 i-rows
        const float* po = off + i_blk * NI + j_base + t;
        #pragma unroll 8
        for (int r = 0; r < 32; ++r) {
            float s, c;
            __sincosf(po[r * NI], &s, &c);
            s_nc[jph * STR + r * 2 + par] = -two_rho * c;
            s_so[jph * STR + r * 2 + par] =  two_rho * s;
        }
        __syncthreads();

        const float* cxb = s_cx + tx * 8;       // 4 b's = 8 floats, pair-interleaved
        const float* sxb = s_sx + tx * 8;
        const float* ncb = s_nc + ty * 8;       // 4 i's = 8 floats
        const float* sob = s_so + ty * 8;

        #pragma unroll 2
        for (int jp = 0; jp < J_CH / 2; jp += 2) {   // 4 j per iteration
            // x-side operands: (b0,b1) and (b2,b3) packed pairs, jp and jp+1
            const ulonglong2 cxA0 = *(const ulonglong2*)(cxb + (jp    ) * STR);
            const ulonglong2 cxA1 = *(const ulonglong2*)(cxb + (jp    ) * STR + 4);
            const ulonglong2 cxB0 = *(const ulonglong2*)(cxb + (jp + 1) * STR);
            const ulonglong2 cxB1 = *(const ulonglong2*)(cxb + (jp + 1) * STR + 4);
            const ulonglong2 sxA0 = *(const ulonglong2*)(sxb + (jp    ) * STR);
            const ulonglong2 sxA1 = *(const ulonglong2*)(sxb + (jp    ) * STR + 4);
            const ulonglong2 sxB0 = *(const ulonglong2*)(sxb + (jp + 1) * STR);
            const ulonglong2 sxB1 = *(const ulonglong2*)(sxb + (jp + 1) * STR + 4);
            // o-side operands: (i0,i1) and (i2,i3)
            const ulonglong2 ncA0 = *(const ulonglong2*)(ncb + (jp    ) * STR);
            const ulonglong2 ncA1 = *(const ulonglong2*)(ncb + (jp    ) * STR + 4);
            const ulonglong2 ncB0 = *(const ulonglong2*)(ncb + (jp + 1) * STR);
            const ulonglong2 ncB1 = *(const ulonglong2*)(ncb + (jp + 1) * STR + 4);
            const ulonglong2 soA0 = *(const ulonglong2*)(sob + (jp    ) * STR);
            const ulonglong2 soA1 = *(const ulonglong2*)(sob + (jp    ) * STR + 4);
            const ulonglong2 soB0 = *(const ulonglong2*)(sob + (jp + 1) * STR);
            const ulonglong2 soB1 = *(const ulonglong2*)(sob + (jp + 1) * STR + 4);

            const ull cxv[4] = {cxA0.x, cxA0.y, cxA1.x, cxA1.y};
            const ull sxv[4] = {sxA0.x, sxA0.y, sxA1.x, sxA1.y};
            const ull cxw[4] = {cxB0.x, cxB0.y, cxB1.x, cxB1.y};
            const ull sxw[4] = {sxB0.x, sxB0.y, sxB1.x, sxB1.y};
            const ull ncv[4] = {ncA0.x, ncA0.y, ncA1.x, ncA1.y};
            const ull sov[4] = {soA0.x, soA0.y, soA1.x, soA1.y};
            const ull ncw[4] = {ncB0.x, ncB0.y, ncB1.x, ncB1.y};
            const ull sow[4] = {soB0.x, soB0.y, soB1.x, soB1.y};

            #pragma unroll
            for (int bb = 0; bb < 4; ++bb)
                #pragma unroll
                for (int ii = 0; ii < 4; ++ii)
                    QCELL(acc[bb * 4 + ii],
                          cxv[bb], sxv[bb], cxw[bb], sxw[bb],
                          ncv[ii], sov[ii], ncw[ii], sow[ii]);
        }
    }

    const int b0 = b_blk + tx * 4;
    const int i0 = i_blk + ty * 4;
    #pragma unroll
    for (int bb = 0; bb < 4; ++bb) {
        float4 r;
        r.x = fmaf(negK, acc[bb * 4 + 0], (float)NI);
        r.y = fmaf(negK, acc[bb * 4 + 1], (float)NI);
        r.z = fmaf(negK, acc[bb * 4 + 2], (float)NI);
        r.w = fmaf(negK, acc[bb * 4 + 3], (float)NI);
        *(float4*)(out + (b0 + bb) * NO + i0) = r;
    }
}

extern "C" void kernel_launch(void* const* d_in, const int* in_sizes, int n_in,
                              void* d_out, int out_size) {
    const float* x   = (const float*)d_in[0];   // input_matrix [2048, 256]
    const float* off = (const float*)d_in[1];   // phase_offset [256, 256]
    float* out = (float*)d_out;                 // [2048, 256]

    // Physics constants
    const double PI     = 3.14159265358979323846;
    const double RADIUS = 5e-6;
    const double KAPPA  = 0.1;
    const double N_EFF  = 3.48;
    const double LAMBDA = 1.55e-6;
    const double LOSS_A = 0.99;

    const double t   = sqrt(1.0 - KAPPA);
    const double a   = LOSS_A;
    const double rho = a * t;
    const double phi0 = fmod(2.0 * PI * N_EFF * (2.0 * PI * RADIUS) / LAMBDA, 2.0 * PI);

    const float Qc      = (float)(1.0 + rho * rho);
    const float two_rho = (float)(2.0 * rho);
    const float negK    = (float)(-(1.0 - t * t) * (1.0 - a * a));

    unsigned int qbits;
    memcpy(&qbits, &Qc, 4);
    const ull Q2 = ((ull)qbits << 32) | qbits;   // packed (Qc, Qc)

    dim3 grid(NB / 32, NO / 32);   // (64, 8) = 512 CTAs
    photonic_fused<<<grid, 64>>>(out, x, off, (float)phi0, two_rho, Q2, negK);
}

// round 9
// speedup vs baseline: 1.1040x; 1.1040x over previous
#include <cuda_runtime.h>
#include <math.h>

// Problem dims (fixed by the reference)
#define NB 2048   // batch
#define NI 256    // inner / contraction dim j
#define NO 256    // output dim i

#define J_CH 32                    // j per smem stage
#define NCHUNK (NI / J_CH)         // 8
#define ROWS_CH (J_CH / 2)         // 16 j-pair rows per chunk
// per-buffer float offsets
#define OFF_SX 1024
#define OFF_NC 2048
#define OFF_SO 4096
#define BUF_FLOATS 6144            // 24 KB per buffer
#define BUF_BYTES  24576

typedef unsigned long long ull;

// Global trig tables, pair-interleaved j-major:
//   g_cx2[(j2*R + r)*2 + (j&1)],  R = NB (x-side) or NO (o-side)
__device__ __align__(16) float g_cx2[NI * NB];  // cos(phi0 + x)
__device__ __align__(16) float g_sx2[NI * NB];  // sin(phi0 + x)
__device__ __align__(16) float g_nc2[NI * NO];  // -2*rho*cos(off)
__device__ __align__(16) float g_so2[NI * NO];  //  2*rho*sin(off)

// ---------------- prep: both tables in one launch ----------------
__global__ void prep_all(const float* __restrict__ x, const float* __restrict__ off,
                         float phi0, float two_rho) {
    __shared__ float tile[32][33];
    const int blk = blockIdx.x;
    const float* src;
    float *dc, *ds;
    int R, r0, j0;
    float addp, mc, ms;
    if (blk < 512) {               // x-table: 64 b-tiles x 8 j-tiles
        r0 = (blk >> 3) * 32; j0 = (blk & 7) * 32;
        src = x;  dc = g_cx2; ds = g_sx2; R = NB;
        addp = phi0; mc = 1.0f; ms = 1.0f;
    } else {                       // off-table: 8 i-tiles x 8 j-tiles
        int q = blk - 512;
        r0 = (q >> 3) * 32; j0 = (q & 7) * 32;
        src = off; dc = g_nc2; ds = g_so2; R = NO;
        addp = 0.0f; mc = -two_rho; ms = two_rho;
    }
    const int lane = threadIdx.x & 31;
    const int w8   = threadIdx.x >> 5;
    #pragma unroll
    for (int rr = 0; rr < 4; ++rr)
        tile[w8 + rr * 8][lane] = src[(r0 + w8 + rr * 8) * NI + j0 + lane];
    __syncthreads();
    #pragma unroll
    for (int k = 0; k < 4; ++k) {
        int jj = w8 + k * 8, ri = lane;
        float s, c;
        __sincosf(addp + tile[ri][jj], &s, &c);
        int idx = (((j0 + jj) >> 1) * R + (r0 + ri)) * 2 + (jj & 1);
        dc[idx] = mc * c;
        ds[idx] = ms * s;
    }
}

// ---------------- packed f32x2 + misc helpers ----------------
__device__ __forceinline__ ull ffma2(ull a, ull b, ull c) {
    ull d;
    asm("fma.rn.f32x2 %0, %1, %2, %3;" : "=l"(d) : "l"(a), "l"(b), "l"(c));
    return d;
}
__device__ __forceinline__ ull fadd2(ull a, ull b) {
    ull d;
    asm("add.rn.f32x2 %0, %1, %2;" : "=l"(d) : "l"(a), "l"(b));
    return d;
}
__device__ __forceinline__ ull fmul2(ull a, ull b) {
    ull d;
    asm("mul.rn.f32x2 %0, %1, %2;" : "=l"(d) : "l"(a), "l"(b));
    return d;
}
__device__ __forceinline__ float2 u2f(ull v) {
    float2 r;
    asm("mov.b64 {%0, %1}, %2;" : "=f"(r.x), "=f"(r.y) : "l"(v));
    return r;
}
__device__ __forceinline__ float frcp(float x) {
    float r;
    asm("rcp.approx.f32 %0, %1;" : "=f"(r) : "f"(x));
    return r;
}
__device__ __forceinline__ void cp16(unsigned dst, const void* src) {
    asm volatile("cp.async.ca.shared.global [%0], [%1], 16;\n" :: "r"(dst), "l"(src));
}

// 4 j-terms fused: sum 1/d = (S.x*P.y + S.y*P.x) * rcp(P.x*P.y), S=D+E, P=D*E.
#define QCELL(acc, cA, sA, cB, sB, nA, oA, nB, oB)                     \
    do {                                                               \
        ull D_ = ffma2((cA), (nA), ffma2((sA), (oA), Q2));             \
        ull E_ = ffma2((cB), (nB), ffma2((sB), (oB), Q2));             \
        float2 S_ = u2f(fadd2(D_, E_));                                \
        float2 P_ = u2f(fmul2(D_, E_));                                \
        (acc) = fmaf(fmaf(S_.x, P_.y, S_.y * P_.x),                    \
                     frcp(P_.x * P_.y), (acc));                        \
    } while (0)

// CTA: 256 threads, tile 32(b) x 64(i), micro-tile 2b x 4i (8 accumulators).
// grid (64, 4) = 256 CTAs = 2048 warps. Tables staged via double-buffered cp.async.
__global__ __launch_bounds__(256) void photonic_main(float* __restrict__ out,
                                                     ull Q2, float negK) {
    extern __shared__ __align__(16) float sbuf[];   // 2 * 24 KB

    const int t  = threadIdx.x;
    const int tx = t & 15;                   // 16 groups along b (2 b each)
    const int ty = t >> 4;                   // 16 groups along i (4 i each)
    const int b_blk = blockIdx.x * 32;
    const int i_blk = blockIdx.y * 64;

    // fill coords: row = t>>4 (16 j-pair rows), seg = t&15 (16B segments)
    const int row = t >> 4, seg = t & 15;
    const unsigned sb = (unsigned)__cvta_generic_to_shared(sbuf);

    const float* px_c = g_cx2 + (row * NB + b_blk) * 2 + seg * 4;
    const float* px_s = g_sx2 + (row * NB + b_blk) * 2 + seg * 4;
    const float* po_c = g_nc2 + (row * NO + i_blk) * 2 + seg * 4;
    const float* po_s = g_so2 + (row * NO + i_blk) * 2 + seg * 4;
    const int xstep = ROWS_CH * NB * 2;      // floats per chunk, x-side
    const int ostep = ROWS_CH * NO * 2;      // floats per chunk, o-side

    auto issue = [&](int c, int p) {
        unsigned base = sb + (unsigned)(p * BUF_BYTES);
        unsigned xd = base + (unsigned)((row * 64 + seg * 4) * 4);
        unsigned od = base + (unsigned)((row * 128 + seg * 4) * 4);
        cp16(xd,                    px_c + c * xstep);
        cp16(xd + OFF_SX * 4,       px_s + c * xstep);
        cp16(od + OFF_NC * 4,       po_c + c * ostep);
        cp16(od + OFF_NC * 4 + 256, po_c + c * ostep + 64);
        cp16(od + OFF_SO * 4,       po_s + c * ostep);
        cp16(od + OFF_SO * 4 + 256, po_s + c * ostep + 64);
        asm volatile("cp.async.commit_group;\n" ::);
    };

    float a00 = 0.f, a01 = 0.f, a02 = 0.f, a03 = 0.f;
    float a10 = 0.f, a11 = 0.f, a12 = 0.f, a13 = 0.f;

    issue(0, 0);
    issue(1, 1);

    #pragma unroll 1
    for (int c = 0; c < NCHUNK; ++c) {
        if (c < NCHUNK - 1) asm volatile("cp.async.wait_group 1;\n" ::);
        else                asm volatile("cp.async.wait_group 0;\n" ::);
        __syncthreads();

        const int p = c & 1;
        const float* buf = sbuf + p * BUF_FLOATS;
        const float* cxb = buf +          tx * 4;   // 2 b's, pair-interleaved
        const float* sxb = buf + OFF_SX + tx * 4;
        const float* ncb = buf + OFF_NC + ty * 8;   // 4 i's
        const float* sob = buf + OFF_SO + ty * 8;

        #pragma unroll
        for (int jp = 0; jp < ROWS_CH; jp += 2) {   // 4 j per iter, imm offsets
            const ulonglong2 cxA = *(const ulonglong2*)(cxb + (jp    ) * 64);
            const ulonglong2 cxB = *(const ulonglong2*)(cxb + (jp + 1) * 64);
            const ulonglong2 sxA = *(const ulonglong2*)(sxb + (jp    ) * 64);
            const ulonglong2 sxB = *(const ulonglong2*)(sxb + (jp + 1) * 64);
            const ulonglong2 nA0 = *(const ulonglong2*)(ncb + (jp    ) * 128);
            const ulonglong2 nA1 = *(const ulonglong2*)(ncb + (jp    ) * 128 + 4);
            const ulonglong2 nB0 = *(const ulonglong2*)(ncb + (jp + 1) * 128);
            const ulonglong2 nB1 = *(const ulonglong2*)(ncb + (jp + 1) * 128 + 4);
            const ulonglong2 oA0 = *(const ulonglong2*)(sob + (jp    ) * 128);
            const ulonglong2 oA1 = *(const ulonglong2*)(sob + (jp    ) * 128 + 4);
            const ulonglong2 oB0 = *(const ulonglong2*)(sob + (jp + 1) * 128);
            const ulonglong2 oB1 = *(const ulonglong2*)(sob + (jp + 1) * 128 + 4);

            // b0 row
            QCELL(a00, cxA.x, sxA.x, cxB.x, sxB.x, nA0.x, oA0.x, nB0.x, oB0.x);
            QCELL(a01, cxA.x, sxA.x, cxB.x, sxB.x, nA0.y, oA0.y, nB0.y, oB0.y);
            QCELL(a02, cxA.x, sxA.x, cxB.x, sxB.x, nA1.x, oA1.x, nB1.x, oB1.x);
            QCELL(a03, cxA.x, sxA.x, cxB.x, sxB.x, nA1.y, oA1.y, nB1.y, oB1.y);
            // b0+1 row
            QCELL(a10, cxA.y, sxA.y, cxB.y, sxB.y, nA0.x, oA0.x, nB0.x, oB0.x);
            QCELL(a11, cxA.y, sxA.y, cxB.y, sxB.y, nA0.y, oA0.y, nB0.y, oB0.y);
            QCELL(a12, cxA.y, sxA.y, cxB.y, sxB.y, nA1.x, oA1.x, nB1.x, oB1.x);
            QCELL(a13, cxA.y, sxA.y, cxB.y, sxB.y, nA1.y, oA1.y, nB1.y, oB1.y);
        }
        __syncthreads();   // all reads of buffer p done
        if (c + 2 < NCHUNK) issue(c + 2, p);
    }

    const int b0 = b_blk + tx * 2;
    const int i0 = i_blk + ty * 4;
    float4 r0, r1;
    r0.x = fmaf(negK, a00, (float)NI);
    r0.y = fmaf(negK, a01, (float)NI);
    r0.z = fmaf(negK, a02, (float)NI);
    r0.w = fmaf(negK, a03, (float)NI);
    r1.x = fmaf(negK, a10, (float)NI);
    r1.y = fmaf(negK, a11, (float)NI);
    r1.z = fmaf(negK, a12, (float)NI);
    r1.w = fmaf(negK, a13, (float)NI);
    *(float4*)(out + (b0 + 0) * NO + i0) = r0;
    *(float4*)(out + (b0 + 1) * NO + i0) = r1;
}

extern "C" void kernel_launch(void* const* d_in, const int* in_sizes, int n_in,
                              void* d_out, int out_size) {
    const float* x   = (const float*)d_in[0];   // input_matrix [2048, 256]
    const float* off = (const float*)d_in[1];   // phase_offset [256, 256]
    float* out = (float*)d_out;                 // [2048, 256]

    // Physics constants
    const double PI     = 3.14159265358979323846;
    const double RADIUS = 5e-6;
    const double KAPPA  = 0.1;
    const double N_EFF  = 3.48;
    const double LAMBDA = 1.55e-6;
    const double LOSS_A = 0.99;

    const double t   = sqrt(1.0 - KAPPA);
    const double a   = LOSS_A;
    const double rho = a * t;
    const double phi0 = fmod(2.0 * PI * N_EFF * (2.0 * PI * RADIUS) / LAMBDA, 2.0 * PI);

    const float Qc      = (float)(1.0 + rho * rho);
    const float two_rho = (float)(2.0 * rho);
    const float negK    = (float)(-(1.0 - t * t) * (1.0 - a * a));

    unsigned int qbits;
    memcpy(&qbits, &Qc, 4);
    const ull Q2 = ((ull)qbits << 32) | qbits;   // packed (Qc, Qc)

    prep_all<<<576, 256>>>(x, off, (float)phi0, two_rho);

    const int smem_bytes = 2 * BUF_BYTES;   // 48 KB
    cudaFuncSetAttribute(photonic_main,
                         cudaFuncAttributeMaxDynamicSharedMemorySize, smem_bytes);
    dim3 grid(NB / 32, NO / 64);   // (64, 4) = 256 CTAs
    photonic_main<<<grid, 256, smem_bytes>>>(out, Q2, negK);
}

// round 10
// speedup vs baseline: 1.1645x; 1.0548x over previous
#include <cuda_runtime.h>
#include <math.h>

// Problem dims (fixed by the reference)
#define NB 2048   // batch
#define NI 256    // inner / contraction dim j
#define NO 256    // output dim i

#define J_CH 32                    // j per smem stage
#define NCHUNK (NI / J_CH)         // 8
#define ROWS_CH (J_CH / 2)         // 16 j-pair rows per chunk
// per-buffer float offsets: cx[1024] sx[1024] nc[512] so[512]
#define OFF_SX 1024
#define OFF_NC 2048
#define OFF_SO 2560
#define BUF_FLOATS 3072            // 12 KB per buffer
#define BUF_BYTES  12288

typedef unsigned long long ull;

// Global trig tables, pair-interleaved j-major:
//   g_cx2[(j2*R + r)*2 + (j&1)],  R = NB (x-side) or NO (o-side)
__device__ __align__(16) float g_cx2[NI * NB];  // cos(phi0 + x)
__device__ __align__(16) float g_sx2[NI * NB];  // sin(phi0 + x)
__device__ __align__(16) float g_nc2[NI * NO];  // -2*rho*cos(off)
__device__ __align__(16) float g_so2[NI * NO];  //  2*rho*sin(off)

// ---------------- prep: both tables in one launch ----------------
__global__ void prep_all(const float* __restrict__ x, const float* __restrict__ off,
                         float phi0, float two_rho) {
    __shared__ float tile[32][33];
    const int blk = blockIdx.x;
    const float* src;
    float *dc, *ds;
    int R, r0, j0;
    float addp, mc, ms;
    if (blk < 512) {               // x-table: 64 b-tiles x 8 j-tiles
        r0 = (blk >> 3) * 32; j0 = (blk & 7) * 32;
        src = x;  dc = g_cx2; ds = g_sx2; R = NB;
        addp = phi0; mc = 1.0f; ms = 1.0f;
    } else {                       // off-table: 8 i-tiles x 8 j-tiles
        int q = blk - 512;
        r0 = (q >> 3) * 32; j0 = (q & 7) * 32;
        src = off; dc = g_nc2; ds = g_so2; R = NO;
        addp = 0.0f; mc = -two_rho; ms = two_rho;
    }
    const int lane = threadIdx.x & 31;
    const int w8   = threadIdx.x >> 5;
    #pragma unroll
    for (int rr = 0; rr < 4; ++rr)
        tile[w8 + rr * 8][lane] = src[(r0 + w8 + rr * 8) * NI + j0 + lane];
    __syncthreads();
    #pragma unroll
    for (int k = 0; k < 4; ++k) {
        int jj = w8 + k * 8, ri = lane;
        float s, c;
        __sincosf(addp + tile[ri][jj], &s, &c);
        int idx = (((j0 + jj) >> 1) * R + (r0 + ri)) * 2 + (jj & 1);
        dc[idx] = mc * c;
        ds[idx] = ms * s;
    }
}

// ---------------- packed f32x2 + misc helpers ----------------
__device__ __forceinline__ ull ffma2(ull a, ull b, ull c) {
    ull d;
    asm("fma.rn.f32x2 %0, %1, %2, %3;" : "=l"(d) : "l"(a), "l"(b), "l"(c));
    return d;
}
__device__ __forceinline__ ull fadd2(ull a, ull b) {
    ull d;
    asm("add.rn.f32x2 %0, %1, %2;" : "=l"(d) : "l"(a), "l"(b));
    return d;
}
__device__ __forceinline__ ull fmul2(ull a, ull b) {
    ull d;
    asm("mul.rn.f32x2 %0, %1, %2;" : "=l"(d) : "l"(a), "l"(b));
    return d;
}
__device__ __forceinline__ float2 u2f(ull v) {
    float2 r;
    asm("mov.b64 {%0, %1}, %2;" : "=f"(r.x), "=f"(r.y) : "l"(v));
    return r;
}
__device__ __forceinline__ float frcp(float x) {
    float r;
    asm("rcp.approx.f32 %0, %1;" : "=f"(r) : "f"(x));
    return r;
}
__device__ __forceinline__ void cp16(unsigned dst, const void* src) {
    asm volatile("cp.async.ca.shared.global [%0], [%1], 16;\n" :: "r"(dst), "l"(src));
}

// 4 j-terms fused: sum 1/d = (S.x*P.y + S.y*P.x) * rcp(P.x*P.y), S=D+E, P=D*E.
#define QCELL(acc, cA, sA, cB, sB, nA, oA, nB, oB)                     \
    do {                                                               \
        ull D_ = ffma2((cA), (nA), ffma2((sA), (oA), Q2));             \
        ull E_ = ffma2((cB), (nB), ffma2((sB), (oB), Q2));             \
        float2 S_ = u2f(fadd2(D_, E_));                                \
        float2 P_ = u2f(fmul2(D_, E_));                                \
        (acc) = fmaf(fmaf(S_.x, P_.y, S_.y * P_.x),                    \
                     frcp(P_.x * P_.y), (acc));                        \
    } while (0)

// CTA: 128 threads, tile 32(b) x 16(i), micro-tile 2b x 2i.
// grid (64, 16) = 1024 CTAs -> 6.92 CTAs/SM avg, wave imbalance ~1.01.
__global__ __launch_bounds__(128, 7) void photonic_main(float* __restrict__ out,
                                                        ull Q2, float negK) {
    extern __shared__ __align__(16) float sbuf[];   // 2 * 12 KB

    const int t  = threadIdx.x;
    const int tx = t & 15;                   // 16 groups along b (2 b each)
    const int ty = t >> 4;                   // 8 groups along i (2 i each)
    const int b_blk = blockIdx.x * 32;
    const int i_blk = blockIdx.y * 16;

    const unsigned sb = (unsigned)__cvta_generic_to_shared(sbuf);

    // fill coords: x-tables have 256 16B-chunks each -> threads t and t+128;
    // o-tables have 128 16B-chunks -> thread t.
    const int xr0 = t >> 4,        xs0 = t & 15;          // chunk q = t
    const int xr1 = (t + 128) >> 4, xs1 = t & 15;         // chunk q = t+128
    const int orow = t >> 3,       oseg = t & 7;

    const float* pxc0 = g_cx2 + (xr0 * NB + b_blk) * 2 + xs0 * 4;
    const float* pxc1 = g_cx2 + (xr1 * NB + b_blk) * 2 + xs1 * 4;
    const float* pxs0 = g_sx2 + (xr0 * NB + b_blk) * 2 + xs0 * 4;
    const float* pxs1 = g_sx2 + (xr1 * NB + b_blk) * 2 + xs1 * 4;
    const float* poc  = g_nc2 + (orow * NO + i_blk) * 2 + oseg * 4;
    const float* pos  = g_so2 + (orow * NO + i_blk) * 2 + oseg * 4;
    const int xstep = ROWS_CH * NB * 2;      // 65536 floats per chunk
    const int ostep = ROWS_CH * NO * 2;      // 8192 floats per chunk

    auto issue = [&](int c, int p) {
        unsigned base = sb + (unsigned)(p * BUF_BYTES);
        cp16(base + (unsigned)(t * 16),                    pxc0 + c * xstep);
        cp16(base + (unsigned)((t + 128) * 16),            pxc1 + c * xstep);
        cp16(base + (unsigned)(OFF_SX * 4 + t * 16),       pxs0 + c * xstep);
        cp16(base + (unsigned)(OFF_SX * 4 + (t+128) * 16), pxs1 + c * xstep);
        cp16(base + (unsigned)(OFF_NC * 4 + t * 16),       poc  + c * ostep);
        cp16(base + (unsigned)(OFF_SO * 4 + t * 16),       pos  + c * ostep);
        asm volatile("cp.async.commit_group;\n" ::);
    };

    float a00 = 0.f, a01 = 0.f, a10 = 0.f, a11 = 0.f;

    issue(0, 0);
    issue(1, 1);

    #pragma unroll 1
    for (int c = 0; c < NCHUNK; ++c) {
        if (c < NCHUNK - 1) asm volatile("cp.async.wait_group 1;\n" ::);
        else                asm volatile("cp.async.wait_group 0;\n" ::);
        __syncthreads();

        const int p = c & 1;
        const float* buf = sbuf + p * BUF_FLOATS;
        const float* cxb = buf +          tx * 4;   // 2 b's, pair-interleaved
        const float* sxb = buf + OFF_SX + tx * 4;
        const float* ncb = buf + OFF_NC + ty * 4;   // 2 i's, pair-interleaved
        const float* sob = buf + OFF_SO + ty * 4;

        #pragma unroll
        for (int jp = 0; jp < ROWS_CH; jp += 2) {   // 4 j per iter, imm offsets
            const ulonglong2 cxA = *(const ulonglong2*)(cxb + (jp    ) * 64);
            const ulonglong2 cxB = *(const ulonglong2*)(cxb + (jp + 1) * 64);
            const ulonglong2 sxA = *(const ulonglong2*)(sxb + (jp    ) * 64);
            const ulonglong2 sxB = *(const ulonglong2*)(sxb + (jp + 1) * 64);
            const ulonglong2 nA  = *(const ulonglong2*)(ncb + (jp    ) * 32);
            const ulonglong2 nB  = *(const ulonglong2*)(ncb + (jp + 1) * 32);
            const ulonglong2 oA  = *(const ulonglong2*)(sob + (jp    ) * 32);
            const ulonglong2 oB  = *(const ulonglong2*)(sob + (jp + 1) * 32);

            // (b0, i0) / (b0, i1)
            QCELL(a00, cxA.x, sxA.x, cxB.x, sxB.x, nA.x, oA.x, nB.x, oB.x);
            QCELL(a01, cxA.x, sxA.x, cxB.x, sxB.x, nA.y, oA.y, nB.y, oB.y);
            // (b1, i0) / (b1, i1)
            QCELL(a10, cxA.y, sxA.y, cxB.y, sxB.y, nA.x, oA.x, nB.x, oB.x);
            QCELL(a11, cxA.y, sxA.y, cxB.y, sxB.y, nA.y, oA.y, nB.y, oB.y);
        }
        __syncthreads();   // all reads of buffer p done
        if (c + 2 < NCHUNK) issue(c + 2, p);
    }

    const int b0 = b_blk + tx * 2;
    const int i0 = i_blk + ty * 2;
    float2 r0, r1;
    r0.x = fmaf(negK, a00, (float)NI);
    r0.y = fmaf(negK, a01, (float)NI);
    r1.x = fmaf(negK, a10, (float)NI);
    r1.y = fmaf(negK, a11, (float)NI);
    *(float2*)(out + (b0 + 0) * NO + i0) = r0;
    *(float2*)(out + (b0 + 1) * NO + i0) = r1;
}

extern "C" void kernel_launch(void* const* d_in, const int* in_sizes, int n_in,
                              void* d_out, int out_size) {
    const float* x   = (const float*)d_in[0];   // input_matrix [2048, 256]
    const float* off = (const float*)d_in[1];   // phase_offset [256, 256]
    float* out = (float*)d_out;                 // [2048, 256]

    // Physics constants
    const double PI     = 3.14159265358979323846;
    const double RADIUS = 5e-6;
    const double KAPPA  = 0.1;
    const double N_EFF  = 3.48;
    const double LAMBDA = 1.55e-6;
    const double LOSS_A = 0.99;

    const double t   = sqrt(1.0 - KAPPA);
    const double a   = LOSS_A;
    const double rho = a * t;
    const double phi0 = fmod(2.0 * PI * N_EFF * (2.0 * PI * RADIUS) / LAMBDA, 2.0 * PI);

    const float Qc      = (float)(1.0 + rho * rho);
    const float two_rho = (float)(2.0 * rho);
    const float negK    = (float)(-(1.0 - t * t) * (1.0 - a * a));

    unsigned int qbits;
    memcpy(&qbits, &Qc, 4);
    const ull Q2 = ((ull)qbits << 32) | qbits;   // packed (Qc, Qc)

    prep_all<<<576, 256>>>(x, off, (float)phi0, two_rho);

    const int smem_bytes = 2 * BUF_BYTES;   // 24 KB
    cudaFuncSetAttribute(photonic_main,
                         cudaFuncAttributeMaxDynamicSharedMemorySize, smem_bytes);
    dim3 grid(NB / 32, NO / 16);   // (64, 16) = 1024 CTAs
    photonic_main<<<grid, 128, smem_bytes>>>(out, Q2, negK);
}